// round 13
// baseline (speedup 1.0000x reference)
#include <cuda_runtime.h>
#include <math.h>

// GibbsSampler — round 13: 4096-position scheduling chunks (register-cached
// deps), global-position stamps (stamp grid == inverse perm, never cleared),
// raster-ordered wave scatter for phase-2 LDS locality.
//
// Schedule: level(p) = 1 + max(level of earlier conflicting positions),
// conflict = Chebyshev <= 1. Computed once (perm identical across sweeps)
// via chunked fixpoint: in-chunk deps from stamps (global pos), cross-chunk
// base level bl = max Lg over all 8 neighbor cells (covers RAW and WAR:
// every reader is the updater of its own site). Positions counting-sorted by
// level, raster-ordered within each wave. Phase 2: per wave, coalesced loads
// + 8 smem lattice reads + table sample + store; one barrier per wave.
//
// Numerics: bit-exact pipeline from rounds 7-12 (double-precision exp table,
// _rn mul/sub/add/div, sequential cumsum). OUTPUT IS FLOAT32.

#define NSITES 65536
#define NSWEEPS 2
#define BLOCK   1024
#define KPOS    4
#define CHUNK   (BLOCK * KPOS)     // 4096
#define NCHUNK  (NSITES / CHUNK)   // 16
#define LMAXH   255

__device__ unsigned short d_site[NSITES];   // wave-sorted site (raster order)
__device__ float          d_r1[NSITES];     // wave-sorted uniforms, sweep 1
__device__ float          d_r2[NSITES];     // wave-sorted uniforms, sweep 2

__global__ __launch_bounds__(BLOCK, 1)
void gibbs_r13(const unsigned int* __restrict__ A,   // X_init or perm
               const unsigned int* __restrict__ B,   // the other one
               const float* __restrict__ U,          // uniforms (2,65536)
               const unsigned int* __restrict__ s0,  // beta or K
               const unsigned int* __restrict__ s1,  // the other one
               float* __restrict__ out)              // FLOAT32 output
{
    extern __shared__ unsigned char dyn[];
    unsigned short* stamp = (unsigned short*)dyn;    // [0,131072): site -> global pos
    unsigned char*  Xs    = dyn;                     // overlays stamp in phase 2
    unsigned char*  Lg    = dyn + 131072;            // [131072,196608): cell level

    __shared__ float4        s_B[729];
    __shared__ unsigned short s_lv[CHUNK];           // in-chunk position levels
    __shared__ int           s_hist[LMAXH + 2];
    __shared__ int           s_start[LMAXH + 2];
    __shared__ int           s_off[LMAXH + 1];
    __shared__ int           s_gmax;
    __shared__ unsigned int  s_maxA, s_maxB;

    const int tid  = threadIdx.x;
    const int lane = tid & 31;

    // ---------- classify inputs ----------
    if (tid == 0) { s_maxA = 0u; s_maxB = 0u; s_gmax = 0; }
    __syncthreads();
    {
        const uint4* A4 = (const uint4*)A;
        const uint4* B4 = (const uint4*)B;
        unsigned int mA = 0u, mB = 0u;
        for (int i = tid; i < NSITES / 4; i += BLOCK) {
            uint4 a = __ldg(&A4[i]);
            uint4 b = __ldg(&B4[i]);
            mA = max(max(max(a.x, a.y), max(a.z, a.w)), mA);
            mB = max(max(max(b.x, b.y), max(b.z, b.w)), mB);
        }
        atomicMax(&s_maxA, mA);
        atomicMax(&s_maxB, mB);
    }
    __syncthreads();
    const int b_is_x = (s_maxB <= 3u) && (s_maxA > 3u);
    const unsigned int* Xw = b_is_x ? B : A;
    const unsigned int* Pw = b_is_x ? A : B;

    const unsigned int w0 = __ldg(s0);
    const unsigned int w1 = __ldg(s1);
    float beta;
    if (w0 == 4u)      beta = __uint_as_float(w1);
    else if (w1 == 4u) beta = __uint_as_float(w0);
    else if (w0 >= 0x3F000000u && w0 < 0x3FC00000u) beta = __uint_as_float(w0);
    else               beta = __uint_as_float(w1);

    // ---------- init: Lg=0, hist=0, boundary table ----------
    for (int i = tid; i < NSITES; i += BLOCK) Lg[i] = 0;
    for (int t = tid; t <= LMAXH + 1; t += BLOCK) s_hist[t] = 0;
    for (int t = tid; t < 729; t += BLOCK) {
        int c0 = t % 9, c1 = (t / 9) % 9, c2 = t / 81;
        int c3 = 8 - c0 - c1 - c2;
        if (c3 >= 0) {
            int cm = max(max(c0, c1), max(c2, c3));
            float bm = __fmul_rn(beta, (float)cm);
            float e0 = (float)exp((double)__fsub_rn(__fmul_rn(beta, (float)c0), bm));
            float e1 = (float)exp((double)__fsub_rn(__fmul_rn(beta, (float)c1), bm));
            float e2 = (float)exp((double)__fsub_rn(__fmul_rn(beta, (float)c2), bm));
            float e3 = (float)exp((double)__fsub_rn(__fmul_rn(beta, (float)c3), bm));
            float s  = __fadd_rn(__fadd_rn(__fadd_rn(e0, e1), e2), e3);
            float a0 = __fdiv_rn(e0, s);
            float a1 = __fadd_rn(a0, __fdiv_rn(e1, s));
            float a2 = __fadd_rn(a1, __fdiv_rn(e2, s));
            float a3 = __fadd_rn(a2, __fdiv_rn(e3, s));
            s_B[t] = make_float4(a0, a1, a2, a3);
        }
    }
    __syncthreads();

    // ---------- PHASE 1: global leveling, 4096-position chunks ----------
    for (int chunk = 0; chunk < NCHUNK; chunk++) {
        const int base = chunk * CHUNK;

        int          site4[KPOS];
        unsigned int dlo[KPOS], dhi[KPOS];   // up to 4 packed u16 dep cps
        int          nd4[KPOS], bl4[KPOS], lv4[KPOS];

        // stamp: global position into the (never-cleared) stamp grid
        #pragma unroll
        for (int k = 0; k < KPOS; k++) {
            int cp = tid + k * BLOCK;
            int s  = (int)(__ldg(&Pw[base + cp]) & 0xFFFFu);
            site4[k] = s;
            stamp[s] = (unsigned short)(base + cp);
        }
        __syncthreads();

        // discovery: base level from Lg (all 8 cells), deps from stamps
        #pragma unroll
        for (int k = 0; k < KPOS; k++) {
            const int cp = tid + k * BLOCK;
            const unsigned int gp = (unsigned)(base + cp);
            const int s = site4[k];
            const int u = s >> 8, v = s & 255;
            const int um = (u > 0)   ? u - 1 : 0;
            const int up = (u < 255) ? u + 1 : 255;
            const int vm = (v > 0)   ? v - 1 : 0;
            const int vp = (v < 255) ? v + 1 : 255;
            const int ra = um << 8, rb = u << 8, rc = up << 8;
            int na[8];
            na[0] = ra | vm; na[1] = ra | v; na[2] = ra | vp;
            na[3] = rb | vm;                 na[4] = rb | vp;
            na[5] = rc | vm; na[6] = rc | v; na[7] = rc | vp;

            int bl = 0, nd = 0;
            unsigned int lo = 0u, hi = 0u;
            #pragma unroll
            for (int j = 0; j < 8; j++) {
                const int c = na[j];
                bl = max(bl, (int)Lg[c]);
                const unsigned int sv = (unsigned int)stamp[c];
                if (sv >= (unsigned)base && sv < gp) {   // in-chunk earlier dep
                    const unsigned int cpd = sv - (unsigned)base;
                    if      (nd == 0) lo  = cpd;
                    else if (nd == 1) lo |= cpd << 16;
                    else if (nd == 2) hi  = cpd;
                    else if (nd == 3) hi |= cpd << 16;
                    nd++;
                }
            }
            bl4[k] = bl; nd4[k] = nd; dlo[k] = lo; dhi[k] = hi;
            lv4[k] = (nd == 0) ? bl + 1 : 0;
            s_lv[cp] = (unsigned short)lv4[k];
        }
        __syncthreads();

        // fixpoint: lv = 1 + max(bl, dep levels); monotone, one barrier/iter
        for (;;) {
            int anyp = 0;
            #pragma unroll
            for (int k = 0; k < KPOS; k++) {
                if (lv4[k] != 0) continue;
                int ok = 1, mx = bl4[k];
                const int nd = nd4[k];
                if (nd <= 4) {
                    if (nd >= 1) { int l = (int)s_lv[dlo[k] & 0xFFFFu];  ok &= (l != 0); mx = max(mx, l); }
                    if (nd >= 2) { int l = (int)s_lv[dlo[k] >> 16];      ok &= (l != 0); mx = max(mx, l); }
                    if (nd >= 3) { int l = (int)s_lv[dhi[k] & 0xFFFFu];  ok &= (l != 0); mx = max(mx, l); }
                    if (nd >= 4) { int l = (int)s_lv[dhi[k] >> 16];      ok &= (l != 0); mx = max(mx, l); }
                } else {   // rare: >4 deps — rescan stamps
                    const int cp = tid + k * BLOCK;
                    const unsigned int gp = (unsigned)(base + cp);
                    const int s = site4[k];
                    const int u = s >> 8, v = s & 255;
                    const int um = (u > 0)   ? u - 1 : 0;
                    const int up = (u < 255) ? u + 1 : 255;
                    const int vm = (v > 0)   ? v - 1 : 0;
                    const int vp = (v < 255) ? v + 1 : 255;
                    const int ra = um << 8, rb = u << 8, rc = up << 8;
                    const int nb[8] = { ra|vm, ra|v, ra|vp, rb|vm, rb|vp, rc|vm, rc|v, rc|vp };
                    #pragma unroll
                    for (int j = 0; j < 8; j++) {
                        const unsigned int sv = (unsigned int)stamp[nb[j]];
                        if (sv >= (unsigned)base && sv < gp) {
                            int l = (int)s_lv[sv - (unsigned)base];
                            ok &= (l != 0); mx = max(mx, l);
                        }
                    }
                }
                if (ok) {
                    lv4[k] = mx + 1;
                    s_lv[tid + k * BLOCK] = (unsigned short)lv4[k];
                } else anyp = 1;
            }
            if (__syncthreads_count(anyp) == 0) break;
        }

        // commit cell levels
        #pragma unroll
        for (int k = 0; k < KPOS; k++)
            Lg[site4[k]] = (unsigned char)min(lv4[k], LMAXH);
        __syncthreads();
    }

    // ---------- histogram over Lg (warp-aggregated) + gmax ----------
    {
        int wm = 0;
        for (int s = tid; s < NSITES; s += BLOCK) {
            int lv = (int)Lg[s];
            wm = max(wm, lv);
            unsigned m = __match_any_sync(0xFFFFFFFFu, lv);
            if ((int)(__ffs(m) - 1) == lane) atomicAdd(&s_hist[lv], __popc(m));
        }
        wm = __reduce_max_sync(0xFFFFFFFFu, wm);
        if (lane == 0) atomicMax(&s_gmax, wm);
    }
    __syncthreads();

    // ---------- prefix sum ----------
    if (tid == 0) {
        int acc = 0;
        for (int w = 1; w <= LMAXH; w++) { s_start[w] = acc; acc += s_hist[w]; }
        s_start[LMAXH + 1] = acc;
    }
    __syncthreads();
    for (int t = tid; t <= LMAXH; t += BLOCK) s_off[t] = (t >= 1) ? s_start[t] : 0;
    __syncthreads();

    // ---------- raster-ordered scatter: stamp == inverse perm ----------
    for (int s = tid; s < NSITES; s += BLOCK) {
        const int lv  = (int)Lg[s];
        const int pos = (int)stamp[s];
        const float r1 = __ldg(&U[pos]);
        const float r2 = __ldg(&U[NSITES + pos]);
        unsigned m = __match_any_sync(0xFFFFFFFFu, lv);
        const int leader = __ffs(m) - 1;
        const int rank   = __popc(m & ((1u << lane) - 1u));
        int bslot = 0;
        if (lane == leader) bslot = atomicAdd(&s_off[lv], __popc(m));
        bslot = __shfl_sync(0xFFFFFFFFu, bslot, leader);
        const int slot = bslot + rank;
        d_site[slot] = (unsigned short)s;
        d_r1[slot] = r1;
        d_r2[slot] = r2;
    }
    __syncthreads();

    // ---------- load lattice (overlays stamp region) ----------
    for (int i = tid; i < NSITES; i += BLOCK)
        Xs[i] = (unsigned char)(__ldg(&Xw[i]) & 3u);
    const int gmax = min(s_gmax, LMAXH);
    __syncthreads();

    // ---------- PHASE 2: wave-ordered execution, both sweeps ----------
    for (int sweep = 0; sweep < NSWEEPS; sweep++) {
        const float* rsel = sweep ? d_r2 : d_r1;
        for (int w = 1; w <= gmax; w++) {
            const int st = s_start[w];
            const int en = s_start[w + 1];
            for (int t = st + tid; t < en; t += BLOCK) {
                const int site = (int)d_site[t];
                const float r  = rsel[t];
                const int u = site >> 8, v = site & 255;
                const int um = (u > 0)   ? u - 1 : 0;
                const int up = (u < 255) ? u + 1 : 255;
                const int vm = (v > 0)   ? v - 1 : 0;
                const int vp = (v < 255) ? v + 1 : 255;
                const int ra = um << 8, rb = u << 8, rc = up << 8;
                unsigned int acc = 0u;     // byte-packed counts of classes 0-2
                acc += 1u << (((unsigned)Xs[ra | vm]) * 8u);
                acc += 1u << (((unsigned)Xs[ra | v ]) * 8u);
                acc += 1u << (((unsigned)Xs[ra | vp]) * 8u);
                acc += 1u << (((unsigned)Xs[rb | vm]) * 8u);
                acc += 1u << (((unsigned)Xs[rb | vp]) * 8u);
                acc += 1u << (((unsigned)Xs[rc | vm]) * 8u);
                acc += 1u << (((unsigned)Xs[rc | v ]) * 8u);
                acc += 1u << (((unsigned)Xs[rc | vp]) * 8u);
                int c0 = (int)(acc & 0xFFu);
                int c1 = (int)((acc >> 8) & 0xFFu);
                int c2 = (int)((acc >> 16) & 0xFFu);
                float4 b = s_B[c0 + 9 * c1 + 81 * c2];
                int x = (b.x < r) + (b.y < r) + (b.z < r) + (b.w < r);
                Xs[site] = (unsigned char)x;
            }
            __syncthreads();   // wave w writes visible before wave w+1 reads
        }
    }

    // ---------- FLOAT32 output ----------
    for (int i = tid; i < NSITES; i += BLOCK)
        out[i] = (float)Xs[i];
}

extern "C" void kernel_launch(void* const* d_in, const int* in_sizes, int n_in,
                              void* d_out, int out_size)
{
    // element-count mapping: 131072 -> uniforms; 65536 x2 -> X_init/perm; 1 -> scalars
    const void* arr64k[2] = {0, 0}; int n64k = 0;
    const void* scal[2]   = {0, 0}; int nsc = 0;
    const void* unif = 0;
    for (int i = 0; i < n_in; i++) {
        int s = in_sizes[i];
        if (s == 131072) unif = d_in[i];
        else if (s == 65536) { if (n64k < 2) arr64k[n64k++] = d_in[i]; }
        else if (s == 1)     { if (nsc  < 2) scal[nsc++]   = d_in[i]; }
    }
    if (!unif || n64k < 2 || nsc < 1) {
        // positional fallback: X_init, perm, uniforms, beta, K
        arr64k[0] = d_in[0];
        arr64k[1] = (n_in > 1) ? d_in[1] : d_in[0];
        unif      = (n_in > 2) ? d_in[2] : d_in[0];
        scal[0]   = (n_in > 3) ? d_in[3] : d_in[0];
        scal[1]   = (n_in > 4) ? d_in[4] : scal[0];
    }
    if (!scal[1]) scal[1] = scal[0];

    const size_t dyn_bytes = 131072 + 65536;   // stamp/X overlay + Lg
    cudaFuncSetAttribute(gibbs_r13,
                         cudaFuncAttributeMaxDynamicSharedMemorySize,
                         (int)dyn_bytes);
    gibbs_r13<<<1, BLOCK, dyn_bytes>>>((const unsigned int*)arr64k[0],
                                       (const unsigned int*)arr64k[1],
                                       (const float*)unif,
                                       (const unsigned int*)scal[0],
                                       (const unsigned int*)scal[1],
                                       (float*)d_out);
}

// round 14
// speedup vs baseline: 1.0708x; 1.0708x over previous
#include <cuda_runtime.h>
#include <math.h>

// GibbsSampler — round 14: inverse-permutation scheduling (no stamps).
//
// perm is a permutation => each cell updated exactly once per sweep, so
// posG[cell] = scan position (inverse perm, built once) gives each position's
// dependencies directly: the neighbor cells with posG < my position.
// Leveling: unified monotone fixpoint over Lv[cell] (0 = unresolved),
// chunked 1024 positions at a time (earlier chunks fully resolved =>
// in-chunk chains are depth ~2-3). level(i) = 1 + max dep levels; conflicting
// pairs get strictly ordered levels; same-level updates are non-conflicting.
// Positions counting-sorted by level (raster order within a wave) and both
// sweeps execute the wave list with one barrier per wave.
//
// Numerics: bit-exact pipeline from rounds 7-13 (double-precision exp table,
// _rn mul/sub/add/div, sequential cumsum). OUTPUT IS FLOAT32.

#define NSITES 65536
#define NSWEEPS 2
#define BLOCK   1024
#define NCHUNK  64
#define LMAXH   255

__device__ unsigned short d_site[NSITES];   // wave-sorted site (raster order)
__device__ float          d_r1[NSITES];     // wave-sorted uniforms, sweep 1
__device__ float          d_r2[NSITES];     // wave-sorted uniforms, sweep 2

__global__ __launch_bounds__(BLOCK, 1)
void gibbs_r14(const unsigned int* __restrict__ A,   // X_init or perm
               const unsigned int* __restrict__ B,   // the other one
               const float* __restrict__ U,          // uniforms (2,65536)
               const unsigned int* __restrict__ s0,  // beta or K
               const unsigned int* __restrict__ s1,  // the other one
               float* __restrict__ out)              // FLOAT32 output
{
    extern __shared__ unsigned char dyn[];
    unsigned short* posG = (unsigned short*)dyn;     // [0,131072): cell -> position
    unsigned char*  Xs   = dyn;                      // overlays posG in phase 2
    unsigned char*  Lv   = dyn + 131072;             // [131072,196608): cell level

    __shared__ float4       s_B[729];
    __shared__ int          s_hist[LMAXH + 2];
    __shared__ int          s_start[LMAXH + 2];
    __shared__ int          s_off[LMAXH + 1];
    __shared__ int          s_gmax;
    __shared__ unsigned int s_maxA, s_maxB;

    const int tid  = threadIdx.x;
    const int lane = tid & 31;

    // ---------- classification: 1024-sample is provably sufficient ----------
    // (any 1024 DISTINCT values from 0..65535 contain at most four <= 3, so
    //  perm always shows a value > 3; X_init values are all <= 3.)
    if (tid == 0) { s_maxA = 0u; s_maxB = 0u; s_gmax = 0; }
    __syncthreads();
    atomicMax(&s_maxA, __ldg(&A[tid]));
    atomicMax(&s_maxB, __ldg(&B[tid]));

    const unsigned int w0 = __ldg(s0);
    const unsigned int w1 = __ldg(s1);
    float beta;
    if (w0 == 4u)      beta = __uint_as_float(w1);
    else if (w1 == 4u) beta = __uint_as_float(w0);
    else if (w0 >= 0x3F000000u && w0 < 0x3FC00000u) beta = __uint_as_float(w0);
    else               beta = __uint_as_float(w1);
    __syncthreads();
    const int b_is_x = (s_maxB <= 3u) && (s_maxA > 3u);
    const unsigned int* Xw = b_is_x ? B : A;
    const unsigned int* Pw = b_is_x ? A : B;

    // ---------- init: Lv=0, hist=0, boundary table, posG (inverse perm) ----------
    {
        unsigned int* Lv32 = (unsigned int*)Lv;
        for (int i = tid; i < NSITES / 4; i += BLOCK) Lv32[i] = 0u;
    }
    for (int t = tid; t <= LMAXH + 1; t += BLOCK) s_hist[t] = 0;
    for (int t = tid; t < 729; t += BLOCK) {
        int c0 = t % 9, c1 = (t / 9) % 9, c2 = t / 81;
        int c3 = 8 - c0 - c1 - c2;
        if (c3 >= 0) {
            int cm = max(max(c0, c1), max(c2, c3));
            float bm = __fmul_rn(beta, (float)cm);
            float e0 = (float)exp((double)__fsub_rn(__fmul_rn(beta, (float)c0), bm));
            float e1 = (float)exp((double)__fsub_rn(__fmul_rn(beta, (float)c1), bm));
            float e2 = (float)exp((double)__fsub_rn(__fmul_rn(beta, (float)c2), bm));
            float e3 = (float)exp((double)__fsub_rn(__fmul_rn(beta, (float)c3), bm));
            float s  = __fadd_rn(__fadd_rn(__fadd_rn(e0, e1), e2), e3);
            float a0 = __fdiv_rn(e0, s);
            float a1 = __fadd_rn(a0, __fdiv_rn(e1, s));
            float a2 = __fadd_rn(a1, __fdiv_rn(e2, s));
            float a3 = __fadd_rn(a2, __fdiv_rn(e3, s));
            s_B[t] = make_float4(a0, a1, a2, a3);
        }
    }
    for (int p = tid; p < NSITES; p += BLOCK)
        posG[(int)(__ldg(&Pw[p]) & 0xFFFFu)] = (unsigned short)p;
    __syncthreads();

    // ---------- PHASE 1: leveling fixpoint, 64 chunks of 1024 positions ----------
    for (int chunk = 0; chunk < NCHUNK; chunk++) {
        const int pos  = (chunk << 10) + tid;
        const int site = (int)(__ldg(&Pw[pos]) & 0xFFFFu);
        const int u = site >> 8, v = site & 255;
        const int um = (u > 0)   ? u - 1 : 0;
        const int up = (u < 255) ? u + 1 : 255;
        const int vm = (v > 0)   ? v - 1 : 0;
        const int vp = (v < 255) ? v + 1 : 255;
        const int ra = um << 8, rb = u << 8, rc = up << 8;
        const int na0 = ra | vm, na1 = ra | v, na2 = ra | vp;
        const int na3 = rb | vm,               na4 = rb | vp;
        const int na5 = rc | vm, na6 = rc | v, na7 = rc | vp;

        // dependency mask: neighbor cells updated at an earlier position
        // (own cell reads posG == pos -> excluded; later cells excluded)
        unsigned int dm = 0u;
        if ((int)posG[na0] < pos) dm |= 1u;
        if ((int)posG[na1] < pos) dm |= 2u;
        if ((int)posG[na2] < pos) dm |= 4u;
        if ((int)posG[na3] < pos) dm |= 8u;
        if ((int)posG[na4] < pos) dm |= 16u;
        if ((int)posG[na5] < pos) dm |= 32u;
        if ((int)posG[na6] < pos) dm |= 64u;
        if ((int)posG[na7] < pos) dm |= 128u;

        // monotone fixpoint: resolve when all dep cells have a level;
        // earlier chunks are fully resolved, in-chunk chains are depth ~2-3.
        int resolved = 0;
        for (;;) {
            if (!resolved) {
                int ok = 1, mx = 0, l;
                if (dm & 1u)   { l = (int)Lv[na0]; ok &= (l != 0); mx = max(mx, l); }
                if (dm & 2u)   { l = (int)Lv[na1]; ok &= (l != 0); mx = max(mx, l); }
                if (dm & 4u)   { l = (int)Lv[na2]; ok &= (l != 0); mx = max(mx, l); }
                if (dm & 8u)   { l = (int)Lv[na3]; ok &= (l != 0); mx = max(mx, l); }
                if (dm & 16u)  { l = (int)Lv[na4]; ok &= (l != 0); mx = max(mx, l); }
                if (dm & 32u)  { l = (int)Lv[na5]; ok &= (l != 0); mx = max(mx, l); }
                if (dm & 64u)  { l = (int)Lv[na6]; ok &= (l != 0); mx = max(mx, l); }
                if (dm & 128u) { l = (int)Lv[na7]; ok &= (l != 0); mx = max(mx, l); }
                if (ok) { Lv[site] = (unsigned char)min(mx + 1, LMAXH); resolved = 1; }
            }
            if (__syncthreads_count(!resolved) == 0) break;
        }
    }

    // ---------- histogram over cells (coalesced) + gmax ----------
    {
        int wm = 0;
        for (int s = tid; s < NSITES; s += BLOCK) {
            int lv = (int)Lv[s];
            wm = max(wm, lv);
            unsigned m = __match_any_sync(0xFFFFFFFFu, lv);
            if ((int)(__ffs(m) - 1) == lane) atomicAdd(&s_hist[lv], __popc(m));
        }
        wm = __reduce_max_sync(0xFFFFFFFFu, wm);
        if (lane == 0) atomicMax(&s_gmax, wm);
    }
    __syncthreads();

    // ---------- prefix sum ----------
    if (tid == 0) {
        int acc = 0;
        for (int w = 1; w <= LMAXH; w++) { s_start[w] = acc; acc += s_hist[w]; }
        s_start[LMAXH + 1] = acc;
    }
    __syncthreads();
    for (int t = tid; t <= LMAXH; t += BLOCK) s_off[t] = (t >= 1) ? s_start[t] : 0;
    __syncthreads();

    // ---------- raster-ordered scatter (posG gives each cell's uniforms) ----------
    for (int s = tid; s < NSITES; s += BLOCK) {
        const int lv  = (int)Lv[s];
        const int pos = (int)posG[s];
        const float r1 = __ldg(&U[pos]);
        const float r2 = __ldg(&U[NSITES + pos]);
        unsigned m = __match_any_sync(0xFFFFFFFFu, lv);
        const int leader = __ffs(m) - 1;
        const int rank   = __popc(m & ((1u << lane) - 1u));
        int bslot = 0;
        if (lane == leader) bslot = atomicAdd(&s_off[lv], __popc(m));
        bslot = __shfl_sync(0xFFFFFFFFu, bslot, leader);
        const int slot = bslot + rank;
        d_site[slot] = (unsigned short)s;
        d_r1[slot] = r1;
        d_r2[slot] = r2;
    }
    __syncthreads();

    // ---------- load lattice (overlays posG region; posG dead now) ----------
    for (int i = tid; i < NSITES; i += BLOCK)
        Xs[i] = (unsigned char)(__ldg(&Xw[i]) & 3u);
    const int gmax = min(s_gmax, LMAXH);
    __syncthreads();

    // ---------- PHASE 2: wave-ordered execution, both sweeps ----------
    for (int sweep = 0; sweep < NSWEEPS; sweep++) {
        const float* rsel = sweep ? d_r2 : d_r1;
        for (int w = 1; w <= gmax; w++) {
            const int st = s_start[w];
            const int en = s_start[w + 1];
            for (int t = st + tid; t < en; t += BLOCK) {
                const int site = (int)d_site[t];
                const float r  = rsel[t];
                const int u = site >> 8, v = site & 255;
                const int um = (u > 0)   ? u - 1 : 0;
                const int up = (u < 255) ? u + 1 : 255;
                const int vm = (v > 0)   ? v - 1 : 0;
                const int vp = (v < 255) ? v + 1 : 255;
                const int ra = um << 8, rb = u << 8, rc = up << 8;
                unsigned int acc = 0u;     // byte-packed counts of classes 0-2
                acc += 1u << (((unsigned)Xs[ra | vm]) * 8u);
                acc += 1u << (((unsigned)Xs[ra | v ]) * 8u);
                acc += 1u << (((unsigned)Xs[ra | vp]) * 8u);
                acc += 1u << (((unsigned)Xs[rb | vm]) * 8u);
                acc += 1u << (((unsigned)Xs[rb | vp]) * 8u);
                acc += 1u << (((unsigned)Xs[rc | vm]) * 8u);
                acc += 1u << (((unsigned)Xs[rc | v ]) * 8u);
                acc += 1u << (((unsigned)Xs[rc | vp]) * 8u);
                int c0 = (int)(acc & 0xFFu);
                int c1 = (int)((acc >> 8) & 0xFFu);
                int c2 = (int)((acc >> 16) & 0xFFu);
                float4 b = s_B[c0 + 9 * c1 + 81 * c2];
                int x = (b.x < r) + (b.y < r) + (b.z < r) + (b.w < r);
                Xs[site] = (unsigned char)x;
            }
            __syncthreads();   // wave w writes visible before wave w+1 reads
        }
    }

    // ---------- FLOAT32 output ----------
    for (int i = tid; i < NSITES; i += BLOCK)
        out[i] = (float)Xs[i];
}

extern "C" void kernel_launch(void* const* d_in, const int* in_sizes, int n_in,
                              void* d_out, int out_size)
{
    // element-count mapping: 131072 -> uniforms; 65536 x2 -> X_init/perm; 1 -> scalars
    const void* arr64k[2] = {0, 0}; int n64k = 0;
    const void* scal[2]   = {0, 0}; int nsc = 0;
    const void* unif = 0;
    for (int i = 0; i < n_in; i++) {
        int s = in_sizes[i];
        if (s == 131072) unif = d_in[i];
        else if (s == 65536) { if (n64k < 2) arr64k[n64k++] = d_in[i]; }
        else if (s == 1)     { if (nsc  < 2) scal[nsc++]   = d_in[i]; }
    }
    if (!unif || n64k < 2 || nsc < 1) {
        // positional fallback: X_init, perm, uniforms, beta, K
        arr64k[0] = d_in[0];
        arr64k[1] = (n_in > 1) ? d_in[1] : d_in[0];
        unif      = (n_in > 2) ? d_in[2] : d_in[0];
        scal[0]   = (n_in > 3) ? d_in[3] : d_in[0];
        scal[1]   = (n_in > 4) ? d_in[4] : scal[0];
    }
    if (!scal[1]) scal[1] = scal[0];

    const size_t dyn_bytes = 131072 + 65536;   // posG/Xs overlay + Lv
    cudaFuncSetAttribute(gibbs_r14,
                         cudaFuncAttributeMaxDynamicSharedMemorySize,
                         (int)dyn_bytes);
    gibbs_r14<<<1, BLOCK, dyn_bytes>>>((const unsigned int*)arr64k[0],
                                       (const unsigned int*)arr64k[1],
                                       (const float*)unif,
                                       (const unsigned int*)scal[0],
                                       (const unsigned int*)scal[1],
                                       (float*)d_out);
}

// round 16
// speedup vs baseline: 1.6021x; 1.4962x over previous
#include <cuda_runtime.h>
#include <math.h>

// GibbsSampler — round 16: sweep 1 fused with schedule recording.
//
// posG = inverse permutation (built once, read-only). Sweep 1 executes with
// the R8-proven block-synchronous wave loop (deps = neighbor cells whose
// posG lies in [chunk_base, my_pos); execute when all dep done-flags set;
// 2 barriers per wave iteration) and RECORDS the wave index of each update
// as its level. Sweep 2 replays the R11-proven level-wave execution using
// the recorded levels (valid: conflicting pairs get strictly increasing
// waves; same-wave updates are pairwise non-conflicting). The standalone
// scheduling pass of R11/R12 is deleted entirely.
//
// Numerics: bit-exact pipeline from rounds 7-14 (double-precision exp table,
// _rn mul/sub/add/div, sequential cumsum). OUTPUT IS FLOAT32.

#define NSITES 65536
#define NSWEEPS 2
#define BLOCK   1024
#define NCHUNK  64

__device__ unsigned char g_lvl[NSITES];   // per-position wave level (sweep 1)

__global__ __launch_bounds__(BLOCK, 1)
void gibbs_r16(const unsigned int* __restrict__ A,   // X_init or perm
               const unsigned int* __restrict__ B,   // the other one
               const float* __restrict__ U,          // uniforms (2,65536)
               const unsigned int* __restrict__ s0,  // beta or K
               const unsigned int* __restrict__ s1,  // the other one
               float* __restrict__ out)              // FLOAT32 output
{
    extern __shared__ unsigned char dyn[];
    unsigned short* posG = (unsigned short*)dyn;      // [0,131072): cell -> position
    unsigned char*  Xs   = dyn + 131072;              // [131072,196608): lattice

    __shared__ float4        s_B[729];
    __shared__ unsigned char s_done[BLOCK];
    __shared__ int           s_cmax[NCHUNK];
    __shared__ unsigned int  s_maxA, s_maxB;

    const int tid  = threadIdx.x;
    const int lane = tid & 31;

    // ---------- classification: 1024-sample (provably sufficient) ----------
    // any 1024 DISTINCT values from 0..65535 contain at most four <= 3 =>
    // perm always shows a value > 3 in the first 1024; X_init never does.
    if (tid == 0) { s_maxA = 0u; s_maxB = 0u; }
    if (tid < NCHUNK) s_cmax[tid] = 0;
    __syncthreads();
    atomicMax(&s_maxA, __ldg(&A[tid]));
    atomicMax(&s_maxB, __ldg(&B[tid]));

    const unsigned int w0 = __ldg(s0);
    const unsigned int w1 = __ldg(s1);
    float beta;
    if (w0 == 4u)      beta = __uint_as_float(w1);
    else if (w1 == 4u) beta = __uint_as_float(w0);
    else if (w0 >= 0x3F000000u && w0 < 0x3FC00000u) beta = __uint_as_float(w0);
    else               beta = __uint_as_float(w1);
    __syncthreads();
    const int b_is_x = (s_maxB <= 3u) && (s_maxA > 3u);
    const unsigned int* Xw = b_is_x ? B : A;
    const unsigned int* Pw = b_is_x ? A : B;

    // ---------- boundary table (bit-exact) ----------
    for (int t = tid; t < 729; t += BLOCK) {
        int c0 = t % 9, c1 = (t / 9) % 9, c2 = t / 81;
        int c3 = 8 - c0 - c1 - c2;
        if (c3 >= 0) {
            int cm = max(max(c0, c1), max(c2, c3));
            float bm = __fmul_rn(beta, (float)cm);
            float e0 = (float)exp((double)__fsub_rn(__fmul_rn(beta, (float)c0), bm));
            float e1 = (float)exp((double)__fsub_rn(__fmul_rn(beta, (float)c1), bm));
            float e2 = (float)exp((double)__fsub_rn(__fmul_rn(beta, (float)c2), bm));
            float e3 = (float)exp((double)__fsub_rn(__fmul_rn(beta, (float)c3), bm));
            float s  = __fadd_rn(__fadd_rn(__fadd_rn(e0, e1), e2), e3);
            float a0 = __fdiv_rn(e0, s);
            float a1 = __fadd_rn(a0, __fdiv_rn(e1, s));
            float a2 = __fadd_rn(a1, __fdiv_rn(e2, s));
            float a3 = __fadd_rn(a2, __fdiv_rn(e3, s));
            s_B[t] = make_float4(a0, a1, a2, a3);
        }
    }

    // ---------- posG (inverse perm) + lattice ----------
    for (int p = tid; p < NSITES; p += BLOCK)
        posG[(int)(__ldg(&Pw[p]) & 0xFFFFu)] = (unsigned short)p;
    for (int i = tid; i < NSITES; i += BLOCK)
        Xs[i] = (unsigned char)(__ldg(&Xw[i]) & 3u);
    __syncthreads();

    // ================= SWEEP 1: wave execution + level recording =================
    for (int chunk = 0; chunk < NCHUNK; chunk++) {
        const int base = chunk << 10;
        const int idx  = base + tid;
        const int site = (int)(__ldg(&Pw[idx]) & 0xFFFFu);
        const float r  = __ldg(&U[idx]);
        const int u = site >> 8, v = site & 255;
        const int um = (u > 0)   ? u - 1 : 0;
        const int up = (u < 255) ? u + 1 : 255;
        const int vm = (v > 0)   ? v - 1 : 0;
        const int vp = (v < 255) ? v + 1 : 255;
        const int ra = um << 8, rb = u << 8, rc = up << 8;
        const int na0 = ra | vm, na1 = ra | v, na2 = ra | vp;
        const int na3 = rb | vm,               na4 = rb | vp;
        const int na5 = rc | vm, na6 = rc | v, na7 = rc | vp;

        // deps from posG (read-only): in-chunk earlier positions in my box.
        // Own cell reads posG == idx (excluded); clip-duplicates likewise.
        int sp0, sp1, sp2, sp3, sp4, sp5, sp6, sp7, p;
        p = (int)posG[na0]; sp0 = (p >= base && p < idx) ? (p - base) : -1;
        p = (int)posG[na1]; sp1 = (p >= base && p < idx) ? (p - base) : -1;
        p = (int)posG[na2]; sp2 = (p >= base && p < idx) ? (p - base) : -1;
        p = (int)posG[na3]; sp3 = (p >= base && p < idx) ? (p - base) : -1;
        p = (int)posG[na4]; sp4 = (p >= base && p < idx) ? (p - base) : -1;
        p = (int)posG[na5]; sp5 = (p >= base && p < idx) ? (p - base) : -1;
        p = (int)posG[na6]; sp6 = (p >= base && p < idx) ? (p - base) : -1;
        p = (int)posG[na7]; sp7 = (p >= base && p < idx) ? (p - base) : -1;

        s_done[tid] = 0;
        __syncthreads();     // reset visible; prior chunk fully committed

        int mydone = 0, myl = 0, wave = 0;
        for (;;) {
            wave++;
            int ready = 0;
            if (!mydone) {
                ready = 1;
                if (sp0 >= 0) ready &= (int)s_done[sp0];
                if (sp1 >= 0) ready &= (int)s_done[sp1];
                if (sp2 >= 0) ready &= (int)s_done[sp2];
                if (sp3 >= 0) ready &= (int)s_done[sp3];
                if (sp4 >= 0) ready &= (int)s_done[sp4];
                if (sp5 >= 0) ready &= (int)s_done[sp5];
                if (sp6 >= 0) ready &= (int)s_done[sp6];
                if (sp7 >= 0) ready &= (int)s_done[sp7];
            }
            __syncthreads();          // done-reads before X/done writes
            if (ready) {
                unsigned int acc = 0u;   // byte-packed counts of classes 0-2
                acc += 1u << (((unsigned)Xs[na0]) * 8u);
                acc += 1u << (((unsigned)Xs[na1]) * 8u);
                acc += 1u << (((unsigned)Xs[na2]) * 8u);
                acc += 1u << (((unsigned)Xs[na3]) * 8u);
                acc += 1u << (((unsigned)Xs[na4]) * 8u);
                acc += 1u << (((unsigned)Xs[na5]) * 8u);
                acc += 1u << (((unsigned)Xs[na6]) * 8u);
                acc += 1u << (((unsigned)Xs[na7]) * 8u);
                int c0 = (int)(acc & 0xFFu);
                int c1 = (int)((acc >> 8) & 0xFFu);
                int c2 = (int)((acc >> 16) & 0xFFu);
                float4 b = s_B[c0 + 9 * c1 + 81 * c2];
                int x = (b.x < r) + (b.y < r) + (b.z < r) + (b.w < r);
                Xs[site] = (unsigned char)x;
                s_done[tid] = 1;
                mydone = 1;
                myl = wave;
            }
            if (__syncthreads_count(!mydone) == 0) break;
        }

        // record the schedule for sweep 2
        g_lvl[idx] = (unsigned char)myl;
        int wm = __reduce_max_sync(0xFFFFFFFFu, myl);
        if (lane == 0) atomicMax(&s_cmax[chunk], wm);
    }
    __syncthreads();    // s_cmax + last chunk's Xs committed

    // ================= SWEEP 2: replay recorded level waves =================
    for (int chunk = 0; chunk < NCHUNK; chunk++) {
        const int base = chunk << 10;
        const int idx  = base + tid;
        const int site = (int)(__ldg(&Pw[idx]) & 0xFFFFu);
        const float r  = __ldg(&U[NSITES + idx]);
        const int  myl = (int)g_lvl[idx];
        const int cmax = s_cmax[chunk];
        const int u = site >> 8, v = site & 255;
        const int um = (u > 0)   ? u - 1 : 0;
        const int up = (u < 255) ? u + 1 : 255;
        const int vm = (v > 0)   ? v - 1 : 0;
        const int vp = (v < 255) ? v + 1 : 255;
        const int ra = um << 8, rb = u << 8, rc = up << 8;

        for (int w = 1; w <= cmax; w++) {
            if (myl == w) {
                unsigned int acc = 0u;
                acc += 1u << (((unsigned)Xs[ra | vm]) * 8u);
                acc += 1u << (((unsigned)Xs[ra | v ]) * 8u);
                acc += 1u << (((unsigned)Xs[ra | vp]) * 8u);
                acc += 1u << (((unsigned)Xs[rb | vm]) * 8u);
                acc += 1u << (((unsigned)Xs[rb | vp]) * 8u);
                acc += 1u << (((unsigned)Xs[rc | vm]) * 8u);
                acc += 1u << (((unsigned)Xs[rc | v ]) * 8u);
                acc += 1u << (((unsigned)Xs[rc | vp]) * 8u);
                int c0 = (int)(acc & 0xFFu);
                int c1 = (int)((acc >> 8) & 0xFFu);
                int c2 = (int)((acc >> 16) & 0xFFu);
                float4 b = s_B[c0 + 9 * c1 + 81 * c2];
                int x = (b.x < r) + (b.y < r) + (b.z < r) + (b.w < r);
                Xs[site] = (unsigned char)x;
            }
            __syncthreads();   // wave w writes before wave w+1 reads
        }
    }

    // ---------- FLOAT32 output ----------
    for (int i = tid; i < NSITES; i += BLOCK)
        out[i] = (float)Xs[i];
}

extern "C" void kernel_launch(void* const* d_in, const int* in_sizes, int n_in,
                              void* d_out, int out_size)
{
    // element-count mapping: 131072 -> uniforms; 65536 x2 -> X_init/perm; 1 -> scalars
    const void* arr64k[2] = {0, 0}; int n64k = 0;
    const void* scal[2]   = {0, 0}; int nsc = 0;
    const void* unif = 0;
    for (int i = 0; i < n_in; i++) {
        int s = in_sizes[i];
        if (s == 131072) unif = d_in[i];
        else if (s == 65536) { if (n64k < 2) arr64k[n64k++] = d_in[i]; }
        else if (s == 1)     { if (nsc  < 2) scal[nsc++]   = d_in[i]; }
    }
    if (!unif || n64k < 2 || nsc < 1) {
        // positional fallback: X_init, perm, uniforms, beta, K
        arr64k[0] = d_in[0];
        arr64k[1] = (n_in > 1) ? d_in[1] : d_in[0];
        unif      = (n_in > 2) ? d_in[2] : d_in[0];
        scal[0]   = (n_in > 3) ? d_in[3] : d_in[0];
        scal[1]   = (n_in > 4) ? d_in[4] : scal[0];
    }
    if (!scal[1]) scal[1] = scal[0];

    const size_t dyn_bytes = 131072 + 65536;   // posG + Xs
    cudaFuncSetAttribute(gibbs_r16,
                         cudaFuncAttributeMaxDynamicSharedMemorySize,
                         (int)dyn_bytes);
    gibbs_r16<<<1, BLOCK, dyn_bytes>>>((const unsigned int*)arr64k[0],
                                       (const unsigned int*)arr64k[1],
                                       (const float*)unif,
                                       (const unsigned int*)scal[0],
                                       (const unsigned int*)scal[1],
                                       (float*)d_out);
}